// round 14
// baseline (speedup 1.0000x reference)
#include <cuda_runtime.h>
#include <math_constants.h>

#define NROWS 8192
#define IN_DIM 128
#define HID 256
#define SLOPE 0.01f
#define S_CONST 8192.0f

// ---------------- scratch (__device__ globals; no allocs allowed) ----------
__device__ __align__(16) float g_Ppart[32 * 256 * HID];  // [r][kb][c] split-K partials (8 MB)
__device__ __align__(16) float g_v[NROWS];               // normalized flat[:8192]
__device__ __align__(16) float g_Upart[32 * IN_DIM];     // per-v-row partials of v^T X

// ---------------- kernel A (fused): register-tiled GEMM -> Ep partials -----
// grid 512 blocks: kb = bid>>1 (32-row chunk), ch = bid&1 (128-col half).
// 256 threads; thread (ty,tx) owns 4 rows x cols {4tx..4tx+3}.
// W double-buffered in smem [k][col] pitch 132; W read = 1 LDS.128 per kk.
__global__ void __launch_bounds__(256) k_zhe(
        const float* __restrict__ X, const float* __restrict__ W,
        const float* __restrict__ b, const float* __restrict__ E,
        const float* __restrict__ Ai, const float* __restrict__ Aj) {
    __shared__ float Xs[32 * 132];                // [row][k], pitch 132 (16B-aligned)
    __shared__ __align__(16) float Es[32][32];    // [kk][r]: broadcast float4 reads
    __shared__ __align__(16) float Ws[2][32 * 132]; // W chunk [k][col], double-buffered
    __shared__ float sred[128];
    float* const Hs = &Ws[0][0];                  // aliases buffer 0 after mainloop
    const int t  = threadIdx.x;
    const int tx = t & 31;
    const int ty = t >> 5;                        // 0..7 (constant per warp)
    const int kb = blockIdx.x >> 1;
    const int ch = blockIdx.x & 1;
    const int r0 = kb * 32;                       // row base == E k-chunk base
    const int c0 = ch * 128;                      // column-half base

    if (t < 128) sred[t] = Ai[t] + Aj[t];

    {   // X tile: [row][k], pitch 132 floats; float4 loads/stores
        const float4* X4 = (const float4*)(X + (size_t)r0 * IN_DIM);
        for (int i = t; i < 32 * 32; i += 256) {
            int r = i >> 5, k4 = i & 31;
            *(float4*)&Xs[r * 132 + k4 * 4] = X4[i];
        }
    }
    // E tile: rows 0..31, cols r0..r0+31, layout [kk][r]
    for (int i = t; i < 32 * 32; i += 256) {
        int r = i & 31, kk = i >> 5;
        Es[kk][r] = E[(size_t)r * NROWS + r0 + kk];
    }

    // stage W chunk 0 into buffer 0 (lane tx = k_local; coalesced LDG)
    {
        const float* Wsrc = W + (size_t)c0 * IN_DIM + tx;
#pragma unroll 4
        for (int col = ty; col < 128; col += 8)
            Ws[0][tx * 132 + col] = Wsrc[(size_t)col * IN_DIM];
    }
    __syncthreads();

    // finish s-reduction
    if (t < 64) sred[t] += sred[t + 64];
    __syncthreads();
    if (t < 32) {
        float x = sred[t] + sred[t + 32];
#pragma unroll
        for (int o = 16; o > 0; o >>= 1) x += __shfl_xor_sync(0xffffffffu, x, o);
        if (t == 0) sred[0] = x;
    }
    __syncthreads();
    const float s = sred[0];

    // ---- GEMM mainloop, double-buffered ----
    float acc[4][4];
#pragma unroll
    for (int rr = 0; rr < 4; rr++)
#pragma unroll
        for (int q = 0; q < 4; q++) acc[rr][q] = 0.f;

#pragma unroll 1
    for (int kc = 0; kc < 4; kc++) {
        const int buf = kc & 1;
        if (kc < 3) {   // prefetch next chunk into the other buffer
            const float* Wsrc = W + (size_t)c0 * IN_DIM + (kc + 1) * 32 + tx;
            float* dst = &Ws[buf ^ 1][0];
#pragma unroll 4
            for (int col = ty; col < 128; col += 8)
                dst[tx * 132 + col] = Wsrc[(size_t)col * IN_DIM];
        }

        const float* Wb   = &Ws[buf][0];
        const float* Xrow = Xs + kc * 32;
#pragma unroll 4
        for (int kl = 0; kl < 32; kl += 4) {
            float4 xv[4];
#pragma unroll
            for (int rr = 0; rr < 4; rr++)     // warp-uniform broadcast LDS.128
                xv[rr] = *(const float4*)&Xrow[(ty * 4 + rr) * 132 + kl];

#pragma unroll
            for (int kk = 0; kk < 4; kk++) {
                float4 wv = *(const float4*)&Wb[(kl + kk) * 132 + 4 * tx]; // 1 LDS.128
#pragma unroll
                for (int rr = 0; rr < 4; rr++) {
                    float xk = (kk == 0) ? xv[rr].x : (kk == 1) ? xv[rr].y
                             : (kk == 2) ? xv[rr].z : xv[rr].w;
                    acc[rr][0] += xk * wv.x;
                    acc[rr][1] += xk * wv.y;
                    acc[rr][2] += xk * wv.z;
                    acc[rr][3] += xk * wv.w;
                }
            }
        }
        __syncthreads();   // chunk consumed; prefetched buffer complete
    }

    // ---- activation; stage h into Hs (aliases Ws buffer 0, pitch 132) ----
    {
        float4 bq = *(const float4*)&b[c0 + 4 * tx];
#pragma unroll
        for (int rr = 0; rr < 4; rr++) {
            const int row = ty * 4 + rr;
            float a0 = (acc[rr][0] + bq.x) * s;
            float a1 = (acc[rr][1] + bq.y) * s;
            float a2 = (acc[rr][2] + bq.z) * s;
            float a3 = (acc[rr][3] + bq.w) * s;
            a0 = a0 > 0.f ? a0 : SLOPE * a0;
            a1 = a1 > 0.f ? a1 : SLOPE * a1;
            a2 = a2 > 0.f ? a2 : SLOPE * a2;
            a3 = a3 > 0.f ? a3 : SLOPE * a3;
            *(float4*)&Hs[row * 132 + 4 * tx] =
                make_float4(__expf(a0), __expf(a1), __expf(a2), __expf(a3));
        }
    }
    __syncthreads();

    // ---- Ep partial: thread t -> (col = t&127, row-half rh = t>>7) ----
    //   acc2[j] = sum_kk E[16rh+j][r0+kk] * h[kk][c0+col]
    const int col = t & 127;
    const int rh  = t >> 7;          // 0 or 1
    float acc2[16];
#pragma unroll
    for (int j = 0; j < 16; j++) acc2[j] = 0.f;

#pragma unroll 4
    for (int kk = 0; kk < 32; kk++) {
        float h = Hs[kk * 132 + col];            // consecutive lanes: conflict-free
        const float4* es4 = (const float4*)Es[kk] + rh * 4;
#pragma unroll
        for (int j4 = 0; j4 < 4; j4++) {
            float4 e = es4[j4];
            acc2[j4 * 4 + 0] += e.x * h;
            acc2[j4 * 4 + 1] += e.y * h;
            acc2[j4 * 4 + 2] += e.z * h;
            acc2[j4 * 4 + 3] += e.w * h;
        }
    }
#pragma unroll
    for (int j = 0; j < 16; j++)
        g_Ppart[((size_t)(rh * 16 + j) * 256 + kb) * HID + c0 + col] = acc2[j];
}

// ---------------- kernel B: reduce partials -> v; also partial of v^T X ----
// grid 32 blocks (one v-row each), 1024 threads
__global__ void k_v(const float* __restrict__ X) {
    __shared__ float sm[16][256];
    __shared__ float red[256];
    __shared__ float vsm[256];
    __shared__ float su[8][128];
    const int t = threadIdx.x;
    const int r = blockIdx.x;

    {   // phase 1: sum 256 kb-partials (contiguous, float4)
        const float4* P4 = (const float4*)(g_Ppart + (size_t)r * 256 * HID);
        const int c4 = t & 63, y = t >> 6;
        float4 a = make_float4(0.f, 0.f, 0.f, 0.f);
#pragma unroll
        for (int m = 0; m < 16; m++) {
            float4 p = P4[(size_t)(y + 16 * m) * 64 + c4];
            a.x += p.x; a.y += p.y; a.z += p.z; a.w += p.w;
        }
        sm[y][c4 * 4 + 0] = a.x;
        sm[y][c4 * 4 + 1] = a.y;
        sm[y][c4 * 4 + 2] = a.z;
        sm[y][c4 * 4 + 3] = a.w;
    }
    __syncthreads();

    float p = 0.f;
    if (t < 256) {
#pragma unroll
        for (int y = 0; y < 16; y++) p += sm[y][t];
        red[t] = p;
    }
    __syncthreads();
    if (t < 128) red[t] += red[t + 128];
    __syncthreads();
    if (t < 64)  red[t] += red[t + 64];
    __syncthreads();
    if (t < 32) {
        float x = red[t] + red[t + 32];
#pragma unroll
        for (int o = 16; o > 0; o >>= 1) x += __shfl_xor_sync(0xffffffffu, x, o);
        if (t == 0) red[0] = x;
    }
    __syncthreads();
    const float inv = 1.0f / red[0];
    if (t < 256) {
        float v = p * inv;
        vsm[t] = v;
        g_v[r * HID + t] = v;
    }
    __syncthreads();

    {   // phase 2: partial t_r[k] = sum_{c<256} v_c * X[256r + c][k]
        const int k = t & 127, jg = t >> 7;     // jg in [0,8)
        float acc = 0.f;
        const float* Xr = X + ((size_t)r * 256 + jg * 32) * IN_DIM + k;
#pragma unroll
        for (int jj = 0; jj < 32; jj++)
            acc += vsm[jg * 32 + jj] * Xr[(size_t)jj * IN_DIM];
        su[jg][k] = acc;
    }
    __syncthreads();
    if (t < 128) {
        float tot = 0.f;
#pragma unroll
        for (int g = 0; g < 8; g++) tot += su[g][t];
        g_Upart[r * IN_DIM + t] = tot;
    }
}

// ---------------- kernel C (fused): out blocks + alpha blocks --------------
// grid = 64 + 8192, 256 threads.
//   bid < 64   : redundant-w + softmax for 128 rows (hides under alpha's DRAM wall)
//   bid >= 64  : alpha[bid-64,:] = (v_i/S) * v  with streaming stores
__global__ void k_final(const float* __restrict__ W, const float* __restrict__ b,
                        float* __restrict__ out, float* __restrict__ alpha) {
    const int t = threadIdx.x;

    if (blockIdx.x < 64) {
        // ---- out path: recompute w from g_Upart (L2-cached), then softmax ----
        __shared__ __align__(16) float ts[128];
        __shared__ float ws[256];

        if (t < 128) {
            float a = 0.f;
#pragma unroll
            for (int rr = 0; rr < 32; rr++) a += g_Upart[rr * IN_DIM + t];
            ts[t] = a;
        }
        __syncthreads();

        {   // w[t] = dot(ts, W[t,:]) / S
            const float4* Wr = (const float4*)(W + (size_t)t * IN_DIM);
            const float4* t4 = (const float4*)ts;
            float d = 0.f;
#pragma unroll
            for (int i = 0; i < 32; i++) {
                float4 wv = Wr[i], tv = t4[i];
                d += wv.x * tv.x + wv.y * tv.y + wv.z * tv.z + wv.w * tv.w;
            }
            ws[t] = d * (1.0f / S_CONST);
        }
        __syncthreads();

        const int lane = t & 31, wid = t >> 5;
        const int rbase = blockIdx.x * 128 + wid * 16;

        float wl[8], bl[8];
#pragma unroll
        for (int q = 0; q < 8; q++) {
            wl[q] = ws[lane + 32 * q];
            bl[q] = b[lane + 32 * q];
        }

        for (int rr = 0; rr < 16; rr++) {
            const int i = rbase + rr;
            const float vi = g_v[i];
            float l[8];
            float m = -CUDART_INF_F;
#pragma unroll
            for (int q = 0; q < 8; q++) {
                l[q] = vi * wl[q] + bl[q];
                m = fmaxf(m, l[q]);
            }
#pragma unroll
            for (int o = 16; o > 0; o >>= 1) m = fmaxf(m, __shfl_xor_sync(0xffffffffu, m, o));
            float sum = 0.f;
#pragma unroll
            for (int q = 0; q < 8; q++) { l[q] = __expf(l[q] - m); sum += l[q]; }
#pragma unroll
            for (int o = 16; o > 0; o >>= 1) sum += __shfl_xor_sync(0xffffffffu, sum, o);
            const float inv = 1.0f / sum;
#pragma unroll
            for (int q = 0; q < 8; q++)
                out[(size_t)i * HID + lane + 32 * q] = l[q] * inv;
        }
    } else {
        // ---- alpha path: one row per block; streaming (evict-first) stores ----
        const int i = blockIdx.x - 64;
        const float a = g_v[i] * (1.0f / S_CONST);
        const float4* v4 = (const float4*)g_v;
        float4* o4 = (float4*)(alpha + (size_t)i * NROWS);
#pragma unroll
        for (int it = 0; it < 8; it++) {
            float4 vv = v4[t + 256 * it];
            __stwt(&o4[t + 256 * it],
                   make_float4(a * vv.x, a * vv.y, a * vv.z, a * vv.w));
        }
    }
}

// ---------------- launch ---------------------------------------------------
extern "C" void kernel_launch(void* const* d_in, const int* in_sizes, int n_in,
                              void* d_out, int out_size) {
    const float* X  = (const float*)d_in[0];
    const float* E  = (const float*)d_in[1];
    const float* W  = (const float*)d_in[2];
    const float* b  = (const float*)d_in[3];
    const float* Ai = (const float*)d_in[4];
    const float* Aj = (const float*)d_in[5];

    float* out   = (float*)d_out;                       // (8192, 256)
    float* alpha = out + (size_t)NROWS * HID;           // (8192, 8192)

    k_zhe  <<<512, 256>>>(X, W, b, E, Ai, Aj);
    k_v    <<<32, 1024>>>(X);
    k_final<<<64 + NROWS, 256>>>(W, b, out, alpha);
}